// round 2
// baseline (speedup 1.0000x reference)
#include <cuda_runtime.h>
#include <math.h>

#define BATCH   16384
#define CCH     72
#define HH      34
#define SAMP    (CCH*HH)      /* 2448 */
#define OUTC    84
#define OSAMP   (OUTC*HH)     /* 2856 */
#define TB      8             /* samples per conv block */
#define RED_BLOCKS 64
#define RED_PER    256        /* samples reduced per block in stage-1 */
#define BN_COUNT   (16384.0f*34.0f)
#define BN_EPS_F   1e-5f

// Scratch (static device globals: allocation-free)
__device__ float g_mult[BATCH*6];          // per-sample multipliers per xxx channel-class
__device__ float g_part[BATCH*144];        // per-sample BN partials (sum, sumsq interleaved per channel)
__device__ float g_part2[RED_BLOCKS*144];  // stage-1 partials
__device__ float g_ss[144];                // scale[72], shift[72]

__device__ __forceinline__ float sigmoidf_(float z) {
    return 1.0f / (1.0f + __expf(-z));
}

// ---------------------------------------------------------------------------
// K1: per-sample gates + BN partial sums + copy x into output channels [0,72)
// one block per sample, 128 threads
// ---------------------------------------------------------------------------
__global__ void __launch_bounds__(128) k1_stats(
    const float* __restrict__ x,
    const float* __restrict__ fcw,
    const float* __restrict__ fcb,
    float* __restrict__ out)
{
    __shared__ float xs[SAMP];
    __shared__ float ws[HH];
    __shared__ float s1[CCH], s2[CCH], sw[CCH];
    __shared__ float lin[6];

    const int b   = blockIdx.x;
    const int tid = threadIdx.x;

    // cooperative vectorized load + x-copy to output
    const float4* xin4 = (const float4*)(x + (size_t)b * SAMP);
    float4*       out4 = (float4*)(out + (size_t)b * OSAMP);
    float4*       xs4  = (float4*)xs;
    #pragma unroll
    for (int i = tid; i < SAMP/4; i += 128) {
        float4 v = xin4[i];
        xs4[i]  = v;
        out4[i] = v;
    }
    if (tid < HH) ws[tid] = fcw[tid];
    __syncthreads();

    // per-channel row sums (threads 0..71)
    if (tid < CCH) {
        float a1 = 0.f, a2 = 0.f, aw = 0.f;
        const float* row = xs + tid * HH;
        #pragma unroll
        for (int h = 0; h < HH; h++) {
            float v = row[h];
            a1 += v; a2 += v * v; aw += v * ws[h];
        }
        s1[tid] = a1; s2[tid] = a2; sw[tid] = aw;
    }
    __syncthreads();

    // group linear terms: lin[G] = (sum of sw over group)/12 + bias
    // G=0 -> x1 block (lin_x11), G=1..5 -> x2g groups 0..4 (lin_m)
    if (tid < 6) {
        float s = 0.f;
        #pragma unroll
        for (int c = 0; c < 12; c++) s += sw[tid * 12 + c];
        lin[tid] = s * (1.0f/12.0f) + fcb[0];
    }
    __syncthreads();

    // xxx channel classes: cls=0 -> x1g (g1), cls=1..4 -> gg (reversed groups),
    // cls=5 -> x_out (ungated). xxx channel tid sources x channel `src`.
    if (tid < CCH) {
        const int cls = tid / 12;
        float mult;
        if (cls == 0)       mult = sigmoidf_(lin[5] + lin[0]);        // g1
        else if (cls == 5)  mult = 1.0f;                              // x_out
        else                mult = sigmoidf_(lin[5 - cls] + lin[5]);  // gates, reversed
        int src;
        if (cls == 0 || cls == 5) src = tid;
        else                      src = tid + 12 * (5 - 2 * cls);

        g_part[(size_t)b * 144 + tid * 2 + 0] = mult * s1[src];
        g_part[(size_t)b * 144 + tid * 2 + 1] = mult * mult * s2[src];
        if ((tid % 12) == 0) g_mult[b * 6 + cls] = mult;
    }
}

// ---------------------------------------------------------------------------
// K2: deterministic stage-1 reduction of BN partials
// ---------------------------------------------------------------------------
__global__ void __launch_bounds__(144) k2_reduce()
{
    const int t   = threadIdx.x;   // column (channel*2 + kind)
    const int blk = blockIdx.x;
    float acc = 0.f;
    size_t base = (size_t)blk * RED_PER * 144 + t;
    #pragma unroll 8
    for (int i = 0; i < RED_PER; i++) acc += g_part[base + (size_t)i * 144];
    g_part2[blk * 144 + t] = acc;
}

// ---------------------------------------------------------------------------
// K2b: finalize BN scale/shift
// ---------------------------------------------------------------------------
__global__ void __launch_bounds__(72) k2b_final(
    const float* __restrict__ gamma,
    const float* __restrict__ beta)
{
    const int c = threadIdx.x;     // 0..71
    float s = 0.f, q = 0.f;
    #pragma unroll 8
    for (int i = 0; i < RED_BLOCKS; i++) {
        s += g_part2[i * 144 + 2 * c + 0];
        q += g_part2[i * 144 + 2 * c + 1];
    }
    const float inv = 1.0f / BN_COUNT;
    float mu    = s * inv;
    float var   = q * inv - mu * mu;
    float scale = gamma[c] * rsqrtf(var + BN_EPS_F);
    g_ss[c]      = scale;
    g_ss[72 + c] = beta[c] - mu * scale;
}

// ---------------------------------------------------------------------------
// K3: recompute xxx -> BN -> relu -> 3-tap H conv -> output channels [72,84)
// blockDim = TB*HH = 272, one thread per (sample, h), 12 oc accumulators
// ---------------------------------------------------------------------------
__global__ void __launch_bounds__(TB*HH) k3_conv(
    const float* __restrict__ x,
    const float* __restrict__ convw,
    float* __restrict__ out)
{
    extern __shared__ float sm[];
    float* hp  = sm;                 // TB * 72 * 36 (padded relu'd xxx, xxx-channel order)
    float* wsm = hp + TB * 2592;     // 2592 weights, layout [(ic*3+k)*12 + oc]
    float* sc  = wsm + 2592;         // 72
    float* sh  = sc + 72;            // 72
    float* ml  = sh + 72;            // TB*6 multipliers (per xxx class)

    const int tid = threadIdx.x;
    const int b0  = blockIdx.x * TB;

    // weights -> smem, transposed so oc is contiguous (float4-able)
    for (int i = tid; i < 2592; i += blockDim.x) {
        int oc = i % 12;
        int k  = (i / 12) % 3;
        int ic = i / 36;
        wsm[i] = convw[oc * 216 + ic * 3 + k];
    }
    if (tid < 72) { sc[tid] = g_ss[tid]; sh[tid] = g_ss[72 + tid]; }
    if (tid < TB * 6) ml[tid] = g_mult[b0 * 6 + tid];
    // zero the H padding (h = -1 and h = 34)
    for (int i = tid; i < TB * CCH * 2; i += blockDim.x) {
        int s = i / (CCH * 2);
        int r = i % (CCH * 2);
        int c = r >> 1;
        hp[s * 2592 + c * 36 + ((r & 1) ? 35 : 0)] = 0.f;
    }
    __syncthreads();

    // stream x, build normalized relu'd xxx in smem (WITH group reversal):
    // x channel c = 12*g + r maps to xxx channel xc = 12*xcls + r,
    // xcls = g for g in {0,5}, else 5-g.
    const float* xin = x + (size_t)b0 * SAMP;
    for (int idx = tid; idx < TB * SAMP; idx += blockDim.x) {
        int s   = idx / SAMP;
        int rem = idx - s * SAMP;
        int c   = rem / HH;
        int h   = rem - c * HH;
        int g   = c / 12;
        int r   = c - g * 12;
        int xcls = (g == 0 || g == 5) ? g : (5 - g);
        int xc   = 12 * xcls + r;
        float v    = xin[idx];
        float mult = ml[s * 6 + xcls];
        float hv   = fmaxf(fmaf(sc[xc], mult * v, sh[xc]), 0.f);
        hp[s * 2592 + xc * 36 + 1 + h] = hv;
    }
    __syncthreads();

    // conv: thread = (s, h)
    const int s = tid / HH;
    const int h = tid - s * HH;

    float acc[12];
    #pragma unroll
    for (int o = 0; o < 12; o++) acc[o] = 0.f;

    const float*  hps = hp + s * 2592 + h;
    const float4* w4  = (const float4*)wsm;

    #pragma unroll 4
    for (int ic = 0; ic < 72; ic++) {
        float v0 = hps[ic * 36 + 0];
        float v1 = hps[ic * 36 + 1];
        float v2 = hps[ic * 36 + 2];
        const float4* wr = w4 + ic * 9;
        #pragma unroll
        for (int q = 0; q < 3; q++) {
            float4 w0 = wr[q];
            float4 w1 = wr[3 + q];
            float4 w2 = wr[6 + q];
            acc[4*q+0] = fmaf(w0.x, v0, fmaf(w1.x, v1, fmaf(w2.x, v2, acc[4*q+0])));
            acc[4*q+1] = fmaf(w0.y, v0, fmaf(w1.y, v1, fmaf(w2.y, v2, acc[4*q+1])));
            acc[4*q+2] = fmaf(w0.z, v0, fmaf(w1.z, v1, fmaf(w2.z, v2, acc[4*q+2])));
            acc[4*q+3] = fmaf(w0.w, v0, fmaf(w1.w, v1, fmaf(w2.w, v2, acc[4*q+3])));
        }
    }

    float* ob = out + (size_t)(b0 + s) * OSAMP + 72 * HH + h;
    #pragma unroll
    for (int o = 0; o < 12; o++) ob[o * HH] = acc[o];
}

// ---------------------------------------------------------------------------
extern "C" void kernel_launch(void* const* d_in, const int* in_sizes, int n_in,
                              void* d_out, int out_size)
{
    const float* x      = (const float*)d_in[0];
    const float* gamma  = (const float*)d_in[1];
    const float* beta   = (const float*)d_in[2];
    const float* conv_w = (const float*)d_in[3];
    const float* fc_w   = (const float*)d_in[4];
    const float* fc_b   = (const float*)d_in[5];
    float* out = (float*)d_out;

    const int B = in_sizes[0] / SAMP;   // 16384

    const int smem_k3 = (TB * 2592 + 2592 + 72 + 72 + TB * 6) * (int)sizeof(float); // ~94 KB
    cudaFuncSetAttribute(k3_conv, cudaFuncAttributeMaxDynamicSharedMemorySize, smem_k3);

    k1_stats<<<B, 128>>>(x, fc_w, fc_b, out);
    k2_reduce<<<RED_BLOCKS, 144>>>();
    k2b_final<<<1, 72>>>(gamma, beta);
    k3_conv<<<B / TB, TB * HH, smem_k3>>>(x, conv_w, out);
}

// round 3
// speedup vs baseline: 1.1869x; 1.1869x over previous
#include <cuda_runtime.h>
#include <math.h>

#define BATCH   16384
#define CCH     72
#define HH      34
#define SAMP    (CCH*HH)      /* 2448 */
#define OUTC    84
#define OSAMP   (OUTC*HH)     /* 2856 */
#define TB      8             /* samples per conv block */
#define RED_BLOCKS 64
#define RED_PER    256
#define BN_COUNT   (16384.0f*34.0f)
#define BN_EPS_F   1e-5f

// Scratch (static device globals: allocation-free)
__device__ float g_mult[BATCH*6];
__device__ float g_part[BATCH*144];
__device__ float g_part2[RED_BLOCKS*144];
__device__ float g_ss[144];                // scale[72], shift[72]

__device__ __forceinline__ float sigmoidf_(float z) {
    return 1.0f / (1.0f + __expf(-z));
}

// packed f32x2 helpers (sm_103a FFMA2)
#define FMA2(d, a, b, c) \
    asm("fma.rn.f32x2 %0, %1, %2, %3;" : "=l"(d) : "l"(a), "l"(b), "l"(c))
#define PACK2(p, v) do { unsigned int _b = __float_as_uint(v); \
    asm("mov.b64 %0, {%1, %1};" : "=l"(p) : "r"(_b)); } while (0)
#define UNPACK2(lo, hi, p) do { unsigned int _l, _h; \
    asm("mov.b64 {%0, %1}, %2;" : "=r"(_l), "=r"(_h) : "l"(p)); \
    lo = __uint_as_float(_l); hi = __uint_as_float(_h); } while (0)

// ---------------------------------------------------------------------------
// K1: per-sample gates + BN partial sums + copy x into output channels [0,72)
// ---------------------------------------------------------------------------
__global__ void __launch_bounds__(128) k1_stats(
    const float* __restrict__ x,
    const float* __restrict__ fcw,
    const float* __restrict__ fcb,
    float* __restrict__ out)
{
    __shared__ float xs[SAMP];
    __shared__ float ws[HH];
    __shared__ float s1[CCH], s2[CCH], sw[CCH];
    __shared__ float lin[6];

    const int b   = blockIdx.x;
    const int tid = threadIdx.x;

    const float4* xin4 = (const float4*)(x + (size_t)b * SAMP);
    float4*       out4 = (float4*)(out + (size_t)b * OSAMP);
    float4*       xs4  = (float4*)xs;
    #pragma unroll
    for (int i = tid; i < SAMP/4; i += 128) {
        float4 v = xin4[i];
        xs4[i]  = v;
        out4[i] = v;
    }
    if (tid < HH) ws[tid] = fcw[tid];
    __syncthreads();

    if (tid < CCH) {
        float a1 = 0.f, a2 = 0.f, aw = 0.f;
        const float* row = xs + tid * HH;
        #pragma unroll
        for (int h = 0; h < HH; h++) {
            float v = row[h];
            a1 += v; a2 += v * v; aw += v * ws[h];
        }
        s1[tid] = a1; s2[tid] = a2; sw[tid] = aw;
    }
    __syncthreads();

    if (tid < 6) {
        float s = 0.f;
        #pragma unroll
        for (int c = 0; c < 12; c++) s += sw[tid * 12 + c];
        lin[tid] = s * (1.0f/12.0f) + fcb[0];
    }
    __syncthreads();

    if (tid < CCH) {
        const int cls = tid / 12;
        float mult;
        if (cls == 0)       mult = sigmoidf_(lin[5] + lin[0]);
        else if (cls == 5)  mult = 1.0f;
        else                mult = sigmoidf_(lin[5 - cls] + lin[5]);
        int src;
        if (cls == 0 || cls == 5) src = tid;
        else                      src = tid + 12 * (5 - 2 * cls);

        g_part[(size_t)b * 144 + tid * 2 + 0] = mult * s1[src];
        g_part[(size_t)b * 144 + tid * 2 + 1] = mult * mult * s2[src];
        if ((tid % 12) == 0) g_mult[b * 6 + cls] = mult;
    }
}

// ---------------------------------------------------------------------------
// K2 / K2b: deterministic BN stat reduction
// ---------------------------------------------------------------------------
__global__ void __launch_bounds__(144) k2_reduce()
{
    const int t   = threadIdx.x;
    const int blk = blockIdx.x;
    float acc = 0.f;
    size_t base = (size_t)blk * RED_PER * 144 + t;
    #pragma unroll 8
    for (int i = 0; i < RED_PER; i++) acc += g_part[base + (size_t)i * 144];
    g_part2[blk * 144 + t] = acc;
}

__global__ void __launch_bounds__(72) k2b_final(
    const float* __restrict__ gamma,
    const float* __restrict__ beta)
{
    const int c = threadIdx.x;
    float s = 0.f, q = 0.f;
    #pragma unroll 8
    for (int i = 0; i < RED_BLOCKS; i++) {
        s += g_part2[i * 144 + 2 * c + 0];
        q += g_part2[i * 144 + 2 * c + 1];
    }
    const float inv = 1.0f / BN_COUNT;
    float mu    = s * inv;
    float var   = q * inv - mu * mu;
    float scale = gamma[c] * rsqrtf(var + BN_EPS_F);
    g_ss[c]      = scale;
    g_ss[72 + c] = beta[c] - mu * scale;
}

// ---------------------------------------------------------------------------
// K3: xxx -> BN -> relu -> 3-tap conv, FFMA2 over oc-pairs
// blockDim = TB*HH = 272, thread = (s, h)
// ---------------------------------------------------------------------------
__global__ void __launch_bounds__(TB*HH) k3_conv(
    const float* __restrict__ x,
    const float* __restrict__ convw,
    float* __restrict__ out)
{
    extern __shared__ float sm[];
    float* hp   = sm;                    // TB*2592 padded relu'd xxx (xxx-chan order)
    float* wsm  = hp  + TB * 2592;       // 2592 weights [(ic*3+k)*12 + oc]
    float* Asl  = wsm + 2592;            // TB*72: per (s, x-chan) combined scale
    float* Bc   = Asl + TB * 72;         // 72: per x-chan shift (sh[xc])
    int*   offc = (int*)(Bc + 72);       // 72: per x-chan dst offset (xc*36)
    float* scx  = (float*)(offc + 72);   // 72: sc[xc] staging
    float* mlsh = scx + 72;              // TB*6 multipliers

    const int tid = threadIdx.x;
    const int b0  = blockIdx.x * TB;

    // weights -> smem, [(ic*3+k)*12 + oc]
    for (int i = tid; i < 2592; i += TB*HH) {
        int oc = i % 12;
        int k  = (i / 12) % 3;
        int ic = i / 36;
        wsm[i] = convw[oc * 216 + ic * 3 + k];
    }
    // per-x-channel mapping tables
    if (tid < 72) {
        int g = tid / 12, r = tid - g * 12;
        int xcls = (g == 0 || g == 5) ? g : (5 - g);
        int xc   = 12 * xcls + r;
        scx[tid]  = g_ss[xc];
        Bc[tid]   = g_ss[72 + xc];
        offc[tid] = xc * 36;
    }
    if (tid < TB * 6) mlsh[tid] = g_mult[b0 * 6 + tid];
    // zero H padding (slots 0 and 35 of each channel row)
    for (int i = tid; i < TB * CCH * 2; i += TB*HH) {
        int s = i / (CCH * 2);
        int r = i - s * (CCH * 2);
        int c = r >> 1;
        hp[s * 2592 + c * 36 + ((r & 1) ? 35 : 0)] = 0.f;
    }
    __syncthreads();

    // Asl[s][c] = sc[xc(c)] * mult[s][xcls(c)]
    for (int i = tid; i < TB * 72; i += TB*HH) {
        int s = i / 72;
        int c = i - s * 72;
        int g = c / 12;
        int xcls = (g == 0 || g == 5) ? g : (5 - g);
        Asl[i] = scx[c] * mlsh[s * 6 + xcls];
    }
    __syncthreads();

    const int s = tid / HH;
    const int h = tid - s * HH;

    // hp build: thread owns (s,h), walks channels with table lookups only
    {
        const float* xr = x + (size_t)(b0 + s) * SAMP + h;
        float*       hb = hp + s * 2592 + 1 + h;
        const float* As = Asl + s * 72;
        #pragma unroll 8
        for (int c = 0; c < 72; c++) {
            float v = xr[c * HH];
            hb[offc[c]] = fmaxf(fmaf(As[c], v, Bc[c]), 0.f);
        }
    }
    __syncthreads();

    // conv: 6 oc-pair accumulators, FFMA2
    unsigned long long acc[6];
    #pragma unroll
    for (int j = 0; j < 6; j++) acc[j] = 0ULL;

    const float* hps = hp + s * 2592 + h;
    const ulonglong2* w16 = (const ulonglong2*)wsm;   // 2 oc-pairs per load

    #pragma unroll 8
    for (int ic = 0; ic < 72; ic++) {
        float v0 = hps[ic * 36 + 0];
        float v1 = hps[ic * 36 + 1];
        float v2 = hps[ic * 36 + 2];
        unsigned long long vp[3];
        PACK2(vp[0], v0);
        PACK2(vp[1], v1);
        PACK2(vp[2], v2);
        #pragma unroll
        for (int t = 0; t < 9; t++) {
            ulonglong2 ww = w16[ic * 9 + t];
            const int k  = t / 3;
            const int j0 = (t % 3) * 2;
            FMA2(acc[j0],     ww.x, vp[k], acc[j0]);
            FMA2(acc[j0 + 1], ww.y, vp[k], acc[j0 + 1]);
        }
    }

    float* ob = out + (size_t)(b0 + s) * OSAMP + 72 * HH + h;
    #pragma unroll
    for (int j = 0; j < 6; j++) {
        float lo, hi;
        UNPACK2(lo, hi, acc[j]);
        ob[(2*j)   * HH] = lo;
        ob[(2*j+1) * HH] = hi;
    }
}

// ---------------------------------------------------------------------------
extern "C" void kernel_launch(void* const* d_in, const int* in_sizes, int n_in,
                              void* d_out, int out_size)
{
    const float* x      = (const float*)d_in[0];
    const float* gamma  = (const float*)d_in[1];
    const float* beta   = (const float*)d_in[2];
    const float* conv_w = (const float*)d_in[3];
    const float* fc_w   = (const float*)d_in[4];
    const float* fc_b   = (const float*)d_in[5];
    float* out = (float*)d_out;

    const int B = in_sizes[0] / SAMP;   // 16384

    const int smem_k3 = (TB*2592 + 2592 + TB*72 + 72 + 72 + 72 + TB*6) * (int)sizeof(float);
    cudaFuncSetAttribute(k3_conv, cudaFuncAttributeMaxDynamicSharedMemorySize, smem_k3);

    k1_stats<<<B, 128>>>(x, fc_w, fc_b, out);
    k2_reduce<<<RED_BLOCKS, 144>>>();
    k2b_final<<<1, 72>>>(gamma, beta);
    k3_conv<<<B / TB, TB * HH, smem_k3>>>(x, conv_w, out);
}